// round 2
// baseline (speedup 1.0000x reference)
#include <cuda_runtime.h>

// Fused Allen-Cahn step, register-rolling vertical blocking.
//   out = ALPHA*x - ALPHA*x^3 + BETA*(N + S + W + E - 4x), replication pad.
// Shape: (16, 1, 1024, 1024) fp32. HBM-bound: 64MB in + 64MB out.

#define ALPHA 400.0f
#define BETA  10000.0f

static constexpr int W = 1024;
static constexpr int H = 1024;
static constexpr int NIMG = 16;
static constexpr int VEC = 4;            // float4
static constexpr int TPB = W / VEC;      // 256 threads = one full row of float4
static constexpr int RPT = 8;            // rows per thread (vertical register blocking)

__device__ __forceinline__ float pt(float x, float n, float s, float w, float e) {
    // x*(ALPHA - 4*BETA) - ALPHA*x^3 + BETA*(n+s+w+e)
    const float c0 = ALPHA - 4.0f * BETA;
    float nb = (n + s) + (w + e);
    return fmaf(BETA, nb, fmaf(c0, x, -ALPHA * x * x * x));
}

__global__ __launch_bounds__(TPB, 4)
void allen_cahn_kernel(const float* __restrict__ in, float* __restrict__ out) {
    const int c4   = threadIdx.x;              // float4 column index
    const int base = c4 * VEC;                 // element column of .x
    const int r0   = blockIdx.x * RPT;         // first row of this block's strip
    const int img  = blockIdx.y;

    const float* __restrict__ ip = in  + (size_t)img * H * W + base;
    float*       __restrict__ op = out + (size_t)img * H * W + base;

    const int lane = c4 & 31;
    const unsigned FULL = 0xFFFFFFFFu;

    // Rolling window: prev, cur (clamped at top edge).
    const int rp = (r0 == 0) ? 0 : r0 - 1;
    float4 prev = *reinterpret_cast<const float4*>(ip + (size_t)rp * W);
    float4 cur  = *reinterpret_cast<const float4*>(ip + (size_t)r0 * W);

#pragma unroll
    for (int i = 0; i < RPT; i++) {
        const int r  = r0 + i;
        const int rn = (r == H - 1) ? r : r + 1;
        float4 nxt = *reinterpret_cast<const float4*>(ip + (size_t)rn * W);

        // Horizontal halo via warp shuffle; warp-boundary lanes load scalar.
        float west = __shfl_up_sync(FULL, cur.w, 1);
        float east = __shfl_down_sync(FULL, cur.x, 1);
        if (lane == 0)  west = (base == 0)       ? cur.x : ip[(size_t)r * W - 1];
        if (lane == 31) east = (base + VEC >= W) ? cur.w : ip[(size_t)r * W + VEC];

        float4 o;
        o.x = pt(cur.x, prev.x, nxt.x, west,  cur.y);
        o.y = pt(cur.y, prev.y, nxt.y, cur.x, cur.z);
        o.z = pt(cur.z, prev.z, nxt.z, cur.y, cur.w);
        o.w = pt(cur.w, prev.w, nxt.w, cur.z, east);

        *reinterpret_cast<float4*>(op + (size_t)r * W) = o;

        prev = cur;
        cur  = nxt;
    }
}

extern "C" void kernel_launch(void* const* d_in, const int* in_sizes, int n_in,
                              void* d_out, int out_size) {
    const float* x0 = (const float*)d_in[0];
    float* out = (float*)d_out;
    dim3 grid(H / RPT, NIMG);
    allen_cahn_kernel<<<grid, TPB>>>(x0, out);
}